// round 3
// baseline (speedup 1.0000x reference)
#include <cuda_runtime.h>
#include <cstdint>
#include <math_constants.h>

// Problem shapes (fixed by the dataset)
#define NQ 2048
#define NS 65536
#define KF 512          // feature dim = 32*16
#define KSEL 16         // top-k

// Scratch: full d2 matrix (2048 x 65536 fp32 = 512 MB) as a device global
// (no cudaMalloc allowed anywhere).
__device__ float g_d2[(size_t)NQ * NS];
__device__ float g_q2[NQ];
__device__ float g_s2[NS];

// ---------------------------------------------------------------------------
// Kernel 1: squared norms of every query and support row (one warp per row)
// ---------------------------------------------------------------------------
__global__ void norms_kernel(const float* __restrict__ q,
                             const float* __restrict__ s) {
    int gw   = (blockIdx.x * blockDim.x + threadIdx.x) >> 5;
    int lane = threadIdx.x & 31;
    if (gw >= NQ + NS) return;
    const float* base = (gw < NQ) ? (q + (size_t)gw * KF)
                                  : (s + (size_t)(gw - NQ) * KF);
    const float4* b4 = (const float4*)base;
    float sum = 0.f;
    #pragma unroll 4
    for (int i = lane; i < KF / 4; i += 32) {
        float4 v = b4[i];
        sum += v.x * v.x + v.y * v.y + v.z * v.z + v.w * v.w;
    }
    #pragma unroll
    for (int o = 16; o; o >>= 1) sum += __shfl_down_sync(0xffffffffu, sum, o);
    if (lane == 0) {
        if (gw < NQ) g_q2[gw] = sum;
        else         g_s2[gw - NQ] = sum;
    }
}

// ---------------------------------------------------------------------------
// Kernel 2: d2[m][n] = q2[m] + s2[n] - 2 * dot(q[m], s[n])
// Classic 128x128x16 SGEMM tile, 256 threads, 8x8 micro-tile per thread.
// Both operands are K-contiguous (row-major, reduce over K).
// ---------------------------------------------------------------------------
__global__ __launch_bounds__(256)
void dist_gemm_kernel(const float* __restrict__ A,   // (NQ, KF)
                      const float* __restrict__ B) { // (NS, KF)
    __shared__ float As[16][128];
    __shared__ float Bs[16][128];

    const int tid = threadIdx.x;
    const int m0  = blockIdx.y * 128;
    const int n0  = blockIdx.x * 128;
    const int tx  = tid & 15;        // 0..15 -> n
    const int ty  = tid >> 4;        // 0..15 -> m
    const int tm  = ty * 8;
    const int tn  = tx * 8;

    float acc[8][8];
    #pragma unroll
    for (int i = 0; i < 8; i++)
        #pragma unroll
        for (int j = 0; j < 8; j++) acc[i][j] = 0.f;

    for (int kt = 0; kt < KF; kt += 16) {
        // Load 128x16 tiles of A and B, transposed into [k][row] layout.
        #pragma unroll
        for (int it = 0; it < 2; it++) {
            int idx = tid + it * 256;      // 0..511
            int r   = idx >> 2;            // 0..127
            int c4  = (idx & 3) * 4;       // 0,4,8,12
            float4 va = *(const float4*)(A + (size_t)(m0 + r) * KF + kt + c4);
            As[c4 + 0][r] = va.x; As[c4 + 1][r] = va.y;
            As[c4 + 2][r] = va.z; As[c4 + 3][r] = va.w;
            float4 vb = *(const float4*)(B + (size_t)(n0 + r) * KF + kt + c4);
            Bs[c4 + 0][r] = vb.x; Bs[c4 + 1][r] = vb.y;
            Bs[c4 + 2][r] = vb.z; Bs[c4 + 3][r] = vb.w;
        }
        __syncthreads();

        #pragma unroll
        for (int k = 0; k < 16; k++) {
            float a[8], b[8];
            #pragma unroll
            for (int i = 0; i < 8; i++) a[i] = As[k][tm + i];
            #pragma unroll
            for (int j = 0; j < 8; j++) b[j] = Bs[k][tn + j];
            #pragma unroll
            for (int i = 0; i < 8; i++)
                #pragma unroll
                for (int j = 0; j < 8; j++)
                    acc[i][j] = fmaf(a[i], b[j], acc[i][j]);
        }
        __syncthreads();
    }

    // Epilogue: d2 = q2 + s2 - 2*dot
    float q2r[8], s2r[8];
    #pragma unroll
    for (int i = 0; i < 8; i++) q2r[i] = g_q2[m0 + tm + i];
    #pragma unroll
    for (int j = 0; j < 8; j++) s2r[j] = g_s2[n0 + tn + j];

    #pragma unroll
    for (int i = 0; i < 8; i++) {
        float* crow = g_d2 + (size_t)(m0 + tm + i) * NS + (n0 + tn);
        float4 o0, o1;
        o0.x = q2r[i] + s2r[0] - 2.f * acc[i][0];
        o0.y = q2r[i] + s2r[1] - 2.f * acc[i][1];
        o0.z = q2r[i] + s2r[2] - 2.f * acc[i][2];
        o0.w = q2r[i] + s2r[3] - 2.f * acc[i][3];
        o1.x = q2r[i] + s2r[4] - 2.f * acc[i][4];
        o1.y = q2r[i] + s2r[5] - 2.f * acc[i][5];
        o1.z = q2r[i] + s2r[6] - 2.f * acc[i][6];
        o1.w = q2r[i] + s2r[7] - 2.f * acc[i][7];
        ((float4*)crow)[0] = o0;
        ((float4*)crow)[1] = o1;
    }
}

// ---------------------------------------------------------------------------
// Kernel 3: per-query top-16 (smallest d2), then weights.
// One block (256 threads) per query row. Each thread keeps a sorted local
// top-16 of its strided slice; 16 rounds of block argmin merge them.
// Tie-break: smaller support index first (matches lax.top_k).
// Output layout (float32): [ indices (NQ*16) | weights (NQ*16) ]
// ---------------------------------------------------------------------------
__global__ __launch_bounds__(256)
void topk_kernel(float* __restrict__ out) {
    const int qrow = blockIdx.x;
    const int tid  = threadIdx.x;
    const float* row = g_d2 + (size_t)qrow * NS;

    float lv[KSEL];
    int   li[KSEL];
    #pragma unroll
    for (int i = 0; i < KSEL; i++) { lv[i] = CUDART_INF_F; li[i] = 0x7fffffff; }
    float worst = CUDART_INF_F;

    for (int j = tid; j < NS; j += 256) {
        float v = row[j];
        if (v < worst) {
            int pos = KSEL - 1;
            #pragma unroll
            for (int t = KSEL - 1; t > 0; t--) {
                if (pos == t && v < lv[t - 1]) {
                    lv[t] = lv[t - 1]; li[t] = li[t - 1]; pos = t - 1;
                }
            }
            lv[pos] = v; li[pos] = j;
            worst = lv[KSEL - 1];
        }
    }

    __shared__ float sv[256];
    __shared__ int   si[256];
    __shared__ float resv[KSEL];
    __shared__ int   resi[KSEL];

    int p = 0;
    for (int r = 0; r < KSEL; r++) {
        sv[tid] = (p < KSEL) ? lv[p] : CUDART_INF_F;
        si[tid] = (p < KSEL) ? li[p] : 0x7fffffff;
        __syncthreads();
        #pragma unroll
        for (int s = 128; s > 0; s >>= 1) {
            if (tid < s) {
                float v2 = sv[tid + s]; int i2 = si[tid + s];
                if (v2 < sv[tid] || (v2 == sv[tid] && i2 < si[tid])) {
                    sv[tid] = v2; si[tid] = i2;
                }
            }
            __syncthreads();
        }
        int winIdx = si[0];
        if (tid == 0) { resv[r] = sv[0]; resi[r] = winIdx; }
        if (p < KSEL && li[p] == winIdx) p++;
        __syncthreads();
    }

    if (tid == 0) {
        float w[KSEL];
        float ssum = 0.f;
        #pragma unroll
        for (int r = 0; r < KSEL; r++) {
            float d = sqrtf(fmaxf(resv[r], 1e-12f));
            w[r] = 1.f / (d + 1e-6f);
            ssum += w[r];
        }
        float inv = 1.f / ssum;
        #pragma unroll
        for (int r = 0; r < KSEL; r++) {
            out[(size_t)qrow * KSEL + r] = (float)resi[r];
            out[(size_t)NQ * KSEL + (size_t)qrow * KSEL + r] = w[r] * inv;
        }
    }
}

// ---------------------------------------------------------------------------
extern "C" void kernel_launch(void* const* d_in, const int* in_sizes, int n_in,
                              void* d_out, int out_size) {
    const float* q = (const float*)d_in[0];  // (2048, 32, 16) -> (2048, 512)
    const float* s = (const float*)d_in[1];  // (65536, 32, 16) -> (65536, 512)
    float* out = (float*)d_out;

    // 1) norms: one warp per row, 8 warps per block
    int rows = NQ + NS;
    int nblocks = (rows * 32 + 255) / 256;
    norms_kernel<<<nblocks, 256>>>(q, s);

    // 2) distance GEMM: grid (NS/128, NQ/128)
    dim3 g(NS / 128, NQ / 128);
    dist_gemm_kernel<<<g, 256>>>(q, s);

    // 3) per-query top-k + weights
    topk_kernel<<<NQ, 256>>>(out);
}

// round 4
// speedup vs baseline: 1.6328x; 1.6328x over previous
#include <cuda_runtime.h>
#include <cuda_bf16.h>
#include <cstdint>
#include <math_constants.h>

// Problem shapes (fixed by the dataset)
#define NQ 2048
#define NS 65536
#define KF 512          // feature dim = 32*16
#define KSEL 16         // top-k
#define NCAND 128       // candidate cap for exact refinement
#define MARGIN 1.0f     // approx-d2 margin (~7.7 sigma of bf16 error)

// Scratch (no cudaMalloc allowed anywhere)
__device__ float g_d2[(size_t)NQ * NS];   // approx d2 (bf16 matmul, fp32 accum)
__device__ float g_q2[NQ];
__device__ float g_s2[NS];
__device__ int   g_cand[(size_t)NQ * NCAND];
__device__ int   g_ccount[NQ];

// ---------------------------------------------------------------------------
// Kernel 1: squared norms of every query and support row (one warp per row)
// ---------------------------------------------------------------------------
__global__ void norms_kernel(const float* __restrict__ q,
                             const float* __restrict__ s) {
    int gw   = (blockIdx.x * blockDim.x + threadIdx.x) >> 5;
    int lane = threadIdx.x & 31;
    if (gw >= NQ + NS) return;
    const float* base = (gw < NQ) ? (q + (size_t)gw * KF)
                                  : (s + (size_t)(gw - NQ) * KF);
    const float4* b4 = (const float4*)base;
    float sum = 0.f;
    #pragma unroll 4
    for (int i = lane; i < KF / 4; i += 32) {
        float4 v = b4[i];
        sum += v.x * v.x + v.y * v.y + v.z * v.z + v.w * v.w;
    }
    #pragma unroll
    for (int o = 16; o; o >>= 1) sum += __shfl_down_sync(0xffffffffu, sum, o);
    if (lane == 0) {
        if (gw < NQ) g_q2[gw] = sum;
        else         g_s2[gw - NQ] = sum;
    }
}

// ---------------------------------------------------------------------------
// Kernel 2: approx d2 via bf16 tensor-core GEMM (mma.sync.m16n8k16).
// Block tile 128x128x32, 256 threads (8 warps, each 64x32), double-buffered
// swizzled smem. A=(NQ,KF) row-major, B=(NS,KF) row-major -> mma row.col.
//
// smem layout per operand tile: 128 rows x 32 bf16 (64B/row), split in four
// 16B chunks c; chunk stored at position c ^ ((row>>1)&3). This makes both
// the 8B stores and all 4B fragment loads bank-conflict-free-ish and keeps
// every ldmatrix-equivalent LDS.32 pattern on 32 distinct banks.
// ---------------------------------------------------------------------------
#define BM 128
#define BN 128
#define BK 32

__global__ __launch_bounds__(256, 1)
void dist_gemm_bf16(const float* __restrict__ A,   // (NQ, KF)
                    const float* __restrict__ B) { // (NS, KF)
    __shared__ __align__(16) __nv_bfloat16 As[2][BM * BK];
    __shared__ __align__(16) __nv_bfloat16 Bs[2][BM * BK];

    const int tid  = threadIdx.x;
    const int warp = tid >> 5;
    const int lane = tid & 31;
    const int m0 = blockIdx.x * BM;       // grid.x = M blocks (16)
    const int n0 = blockIdx.y * BN;       // grid.y = N blocks (512)
    const int wm = (warp & 1) * 64;       // warp tile 64(M) x 32(N)
    const int wn = (warp >> 1) * 32;

    float acc[4][4][4];
    #pragma unroll
    for (int mt = 0; mt < 4; mt++)
        #pragma unroll
        for (int nt = 0; nt < 4; nt++)
            #pragma unroll
            for (int c = 0; c < 4; c++) acc[mt][nt][c] = 0.f;

    float4 ra[4], rb[4];  // gmem staging (4 float4 each operand)

    // ---- gmem tile load into registers (coalesced float4) ----
    auto gload = [&](int kt) {
        #pragma unroll
        for (int it = 0; it < 4; it++) {
            int idx = tid + it * 256;          // 0..1023
            int row = idx >> 3;                // 0..127
            int qc  = idx & 7;                 // float4 column 0..7
            ra[it] = *(const float4*)(A + (size_t)(m0 + row) * KF + kt * BK + qc * 4);
            rb[it] = *(const float4*)(B + (size_t)(n0 + row) * KF + kt * BK + qc * 4);
        }
    };

    // ---- convert + swizzled store to smem ----
    auto sstore = [&](int buf) {
        #pragma unroll
        for (int it = 0; it < 4; it++) {
            int idx = tid + it * 256;
            int row = idx >> 3;
            int qc  = idx & 7;
            int c    = qc >> 1;                 // 16B chunk 0..3
            int half = qc & 1;                  // which 8B half of the chunk
            int pc   = c ^ ((row >> 1) & 3);    // swizzled chunk position
            int off  = row * 64 + pc * 16 + half * 8;
            {
                __nv_bfloat162 v0 = __float22bfloat162_rn(make_float2(ra[it].x, ra[it].y));
                __nv_bfloat162 v1 = __float22bfloat162_rn(make_float2(ra[it].z, ra[it].w));
                uint2 u;
                u.x = *reinterpret_cast<uint32_t*>(&v0);
                u.y = *reinterpret_cast<uint32_t*>(&v1);
                *reinterpret_cast<uint2*>((char*)As[buf] + off) = u;
            }
            {
                __nv_bfloat162 v0 = __float22bfloat162_rn(make_float2(rb[it].x, rb[it].y));
                __nv_bfloat162 v1 = __float22bfloat162_rn(make_float2(rb[it].z, rb[it].w));
                uint2 u;
                u.x = *reinterpret_cast<uint32_t*>(&v0);
                u.y = *reinterpret_cast<uint32_t*>(&v1);
                *reinterpret_cast<uint2*>((char*)Bs[buf] + off) = u;
            }
        }
    };

    // ---- compute one BK=32 slab (two k16 mma steps) ----
    auto compute = [&](int buf) {
        const char* Ab = (const char*)As[buf];
        const char* Bb = (const char*)Bs[buf];
        #pragma unroll
        for (int ks = 0; ks < 2; ks++) {
            const int c0 = ks * 2, c1 = ks * 2 + 1;
            const int by = (lane & 3) * 4;      // byte offset within chunk
            uint32_t afr[4][4], bfr[4][2];
            #pragma unroll
            for (int mt = 0; mt < 4; mt++) {
                int r0 = wm + mt * 16 + (lane >> 2);
                int r1 = r0 + 8;
                afr[mt][0] = *(const uint32_t*)(Ab + r0 * 64 + (c0 ^ ((r0 >> 1) & 3)) * 16 + by);
                afr[mt][1] = *(const uint32_t*)(Ab + r1 * 64 + (c0 ^ ((r1 >> 1) & 3)) * 16 + by);
                afr[mt][2] = *(const uint32_t*)(Ab + r0 * 64 + (c1 ^ ((r0 >> 1) & 3)) * 16 + by);
                afr[mt][3] = *(const uint32_t*)(Ab + r1 * 64 + (c1 ^ ((r1 >> 1) & 3)) * 16 + by);
            }
            #pragma unroll
            for (int nt = 0; nt < 4; nt++) {
                int nr = wn + nt * 8 + (lane >> 2);
                bfr[nt][0] = *(const uint32_t*)(Bb + nr * 64 + (c0 ^ ((nr >> 1) & 3)) * 16 + by);
                bfr[nt][1] = *(const uint32_t*)(Bb + nr * 64 + (c1 ^ ((nr >> 1) & 3)) * 16 + by);
            }
            #pragma unroll
            for (int mt = 0; mt < 4; mt++)
                #pragma unroll
                for (int nt = 0; nt < 4; nt++)
                    asm volatile(
                        "mma.sync.aligned.m16n8k16.row.col.f32.bf16.bf16.f32 "
                        "{%0,%1,%2,%3}, {%4,%5,%6,%7}, {%8,%9}, {%0,%1,%2,%3};\n"
                        : "+f"(acc[mt][nt][0]), "+f"(acc[mt][nt][1]),
                          "+f"(acc[mt][nt][2]), "+f"(acc[mt][nt][3])
                        : "r"(afr[mt][0]), "r"(afr[mt][1]),
                          "r"(afr[mt][2]), "r"(afr[mt][3]),
                          "r"(bfr[nt][0]), "r"(bfr[nt][1]));
        }
    };

    gload(0);
    sstore(0);
    __syncthreads();
    int buf = 0;
    #pragma unroll 1
    for (int kt = 0; kt < KF / BK; kt++) {
        if (kt + 1 < KF / BK) gload(kt + 1);
        compute(buf);
        if (kt + 1 < KF / BK) {
            sstore(buf ^ 1);
            __syncthreads();
            buf ^= 1;
        }
    }

    // ---- epilogue: d2 = q2 + s2 - 2*dot ----
    #pragma unroll
    for (int mt = 0; mt < 4; mt++) {
        int rlo = m0 + wm + mt * 16 + (lane >> 2);
        float q2lo = g_q2[rlo];
        float q2hi = g_q2[rlo + 8];
        #pragma unroll
        for (int nt = 0; nt < 4; nt++) {
            int nc = n0 + wn + nt * 8 + (lane & 3) * 2;
            float s20 = g_s2[nc], s21 = g_s2[nc + 1];
            float2 o;
            o.x = q2lo + s20 - 2.f * acc[mt][nt][0];
            o.y = q2lo + s21 - 2.f * acc[mt][nt][1];
            *(float2*)(g_d2 + (size_t)rlo * NS + nc) = o;
            o.x = q2hi + s20 - 2.f * acc[mt][nt][2];
            o.y = q2hi + s21 - 2.f * acc[mt][nt][3];
            *(float2*)(g_d2 + (size_t)(rlo + 8) * NS + nc) = o;
        }
    }
}

// ---------------------------------------------------------------------------
// Kernel 3: per-query approx top-16 -> threshold -> candidate list.
// One block (256 threads) per query. Pass 1: per-thread top-16 + 16 argmin
// rounds gives T = 16th smallest approx d2. Pass 2: collect all j with
// v <= T + MARGIN (guaranteed superset of exact top-16 given bf16 error).
// ---------------------------------------------------------------------------
__global__ __launch_bounds__(256)
void topk_select_kernel() {
    const int qrow = blockIdx.x;
    const int tid  = threadIdx.x;
    const float* row = g_d2 + (size_t)qrow * NS;

    float lv[KSEL];
    int   li[KSEL];
    #pragma unroll
    for (int i = 0; i < KSEL; i++) { lv[i] = CUDART_INF_F; li[i] = 0x7fffffff; }
    float worst = CUDART_INF_F;

    const float4* row4 = (const float4*)row;
    for (int j4 = tid; j4 < NS / 4; j4 += 256) {
        float4 v4 = row4[j4];
        float vs[4] = {v4.x, v4.y, v4.z, v4.w};
        #pragma unroll
        for (int c = 0; c < 4; c++) {
            float v = vs[c];
            if (v < worst) {
                int j = j4 * 4 + c;
                int pos = KSEL - 1;
                #pragma unroll
                for (int t = KSEL - 1; t > 0; t--) {
                    if (pos == t && v < lv[t - 1]) {
                        lv[t] = lv[t - 1]; li[t] = li[t - 1]; pos = t - 1;
                    }
                }
                lv[pos] = v; li[pos] = j;
                worst = lv[KSEL - 1];
            }
        }
    }

    __shared__ float sv[256];
    __shared__ int   si[256];
    __shared__ float T_s;
    __shared__ int   cnt;

    int p = 0;
    float lastWin = 0.f;
    for (int r = 0; r < KSEL; r++) {
        sv[tid] = (p < KSEL) ? lv[p] : CUDART_INF_F;
        si[tid] = (p < KSEL) ? li[p] : 0x7fffffff;
        __syncthreads();
        #pragma unroll
        for (int s = 128; s > 0; s >>= 1) {
            if (tid < s) {
                float v2 = sv[tid + s]; int i2 = si[tid + s];
                if (v2 < sv[tid] || (v2 == sv[tid] && i2 < si[tid])) {
                    sv[tid] = v2; si[tid] = i2;
                }
            }
            __syncthreads();
        }
        int winIdx = si[0];
        lastWin = sv[0];
        if (r == KSEL - 1 && tid == 0) { T_s = lastWin; cnt = 0; }
        if (p < KSEL && li[p] == winIdx) p++;
        __syncthreads();
    }

    const float thresh = T_s + MARGIN;
    for (int j4 = tid; j4 < NS / 4; j4 += 256) {
        float4 v4 = row4[j4];
        float vs[4] = {v4.x, v4.y, v4.z, v4.w};
        #pragma unroll
        for (int c = 0; c < 4; c++) {
            if (vs[c] <= thresh) {
                int slot = atomicAdd(&cnt, 1);
                if (slot < NCAND) g_cand[(size_t)qrow * NCAND + slot] = j4 * 4 + c;
            }
        }
    }
    __syncthreads();
    if (tid == 0) g_ccount[qrow] = (cnt < NCAND) ? cnt : NCAND;
}

// ---------------------------------------------------------------------------
// Kernel 4: exact fp32 refinement + final top-16 + weights.
// One block (256 threads = 8 warps) per query. Warp per candidate computes
// the exact fp32 distance; then 16 rounds of (value, index) argmin over the
// candidate set; weights from exact distances.
// Output layout (float32): [ indices (NQ*16) | weights (NQ*16) ]
// ---------------------------------------------------------------------------
__global__ __launch_bounds__(256)
void refine_kernel(const float* __restrict__ q,
                   const float* __restrict__ s,
                   float* __restrict__ out) {
    const int qrow = blockIdx.x;
    const int tid  = threadIdx.x;
    const int warp = tid >> 5;
    const int lane = tid & 31;

    __shared__ float qs[KF];
    __shared__ float ev[NCAND];
    __shared__ int   ei[NCAND];
    __shared__ float sv[128];
    __shared__ int   si[128];
    __shared__ float resv[KSEL];
    __shared__ int   resi[KSEL];

    const int m = g_ccount[qrow];

    for (int i = tid; i < KF; i += 256) qs[i] = q[(size_t)qrow * KF + i];
    for (int i = tid; i < NCAND; i += 256) { ev[i] = CUDART_INF_F; ei[i] = 0x7fffffff; }
    __syncthreads();

    const float q2v = g_q2[qrow];
    for (int ci = warp; ci < m; ci += 8) {
        int sidx = g_cand[(size_t)qrow * NCAND + ci];
        const float* srow = s + (size_t)sidx * KF;
        float dot = 0.f;
        #pragma unroll
        for (int t = 0; t < KF / 32; t++)
            dot = fmaf(qs[lane + 32 * t], srow[lane + 32 * t], dot);
        #pragma unroll
        for (int o = 16; o; o >>= 1) dot += __shfl_down_sync(0xffffffffu, dot, o);
        if (lane == 0) {
            ev[ci] = q2v + g_s2[sidx] - 2.f * dot;
            ei[ci] = sidx;
        }
    }
    __syncthreads();

    for (int r = 0; r < KSEL; r++) {
        if (tid < 128) { sv[tid] = ev[tid]; si[tid] = ei[tid]; }
        __syncthreads();
        #pragma unroll
        for (int st = 64; st > 0; st >>= 1) {
            if (tid < st) {
                float v2 = sv[tid + st]; int i2 = si[tid + st];
                if (v2 < sv[tid] || (v2 == sv[tid] && i2 < si[tid])) {
                    sv[tid] = v2; si[tid] = i2;
                }
            }
            __syncthreads();
        }
        if (tid == 0) { resv[r] = sv[0]; resi[r] = si[0]; }
        __syncthreads();
        if (tid < 128 && ei[tid] == si[0]) ev[tid] = CUDART_INF_F;
        __syncthreads();
    }

    if (tid == 0) {
        float w[KSEL];
        float ssum = 0.f;
        #pragma unroll
        for (int r = 0; r < KSEL; r++) {
            float d = sqrtf(fmaxf(resv[r], 1e-12f));
            w[r] = 1.f / (d + 1e-6f);
            ssum += w[r];
        }
        float inv = 1.f / ssum;
        #pragma unroll
        for (int r = 0; r < KSEL; r++) {
            out[(size_t)qrow * KSEL + r] = (float)resi[r];
            out[(size_t)NQ * KSEL + (size_t)qrow * KSEL + r] = w[r] * inv;
        }
    }
}

// ---------------------------------------------------------------------------
extern "C" void kernel_launch(void* const* d_in, const int* in_sizes, int n_in,
                              void* d_out, int out_size) {
    const float* q = (const float*)d_in[0];  // (2048, 32, 16) -> (2048, 512)
    const float* s = (const float*)d_in[1];  // (65536, 32, 16) -> (65536, 512)
    float* out = (float*)d_out;

    // 1) norms
    int rows = NQ + NS;
    int nblocks = (rows * 32 + 255) / 256;
    norms_kernel<<<nblocks, 256>>>(q, s);

    // 2) approx distance GEMM (tensor cores). grid.x = M blocks so each
    //    wave shares B tiles through L2.
    dim3 g(NQ / BM, NS / BN);
    dist_gemm_bf16<<<g, 256>>>(q, s);

    // 3) approx top-16 + candidate collection
    topk_select_kernel<<<NQ, 256>>>();

    // 4) exact refinement + output
    refine_kernel<<<NQ, 256>>>(q, s, out);
}

// round 7
// speedup vs baseline: 1.8901x; 1.1576x over previous
#include <cuda_runtime.h>
#include <cuda_bf16.h>
#include <cstdint>
#include <math_constants.h>

// Problem shapes (fixed by the dataset)
#define NQ 2048
#define NS 65536
#define KF 512          // feature dim = 32*16
#define KSEL 16         // top-k
#define NCAND 128       // candidate cap for exact refinement
#define MARGIN 1.0f     // approx-d2 margin (~7.7 sigma of bf16 error)

// Unified GEMM tiling: CTA covers 128(M) x 256(N); grid (NQ/128, NS/256)
#define GM 128
#define GN 256
#define GBK 64          // bf16 K per slab on tcgen05 path (128B row = SW128 atom)
#define KSLABS (KF / GBK)               // 8
#define A_STAGE_BYTES (GM * 128)        // 16384
#define B_STAGE_BYTES (GN * 128)        // 32768
#define STAGE_BYTES (A_STAGE_BYTES + B_STAGE_BYTES)   // 49152
#define GEMM_DYN_SMEM (1024 + 2 * STAGE_BYTES + 64)

// tcgen05 only exists on the arch-specific (sm_103a / family) targets.
#if defined(__CUDA_ARCH_FEAT_SM103_ALL) || defined(__CUDA_ARCH_FEAT_SM100_ALL) || \
    (defined(__CUDA_ARCH_FAMILY_SPECIFIC__) && (__CUDA_ARCH_FAMILY_SPECIFIC__ >= 1000))
#define HAS_TCGEN05 1
#else
#define HAS_TCGEN05 0
#endif

// Scratch (no cudaMalloc allowed anywhere)
__device__ float g_d2[(size_t)NQ * NS];   // approx d2 (bf16, fp32 accum)
__device__ float g_q2[NQ];
__device__ float g_s2[NS];
__device__ int   g_cand[(size_t)NQ * NCAND];
__device__ int   g_ccount[NQ];
__device__ __nv_bfloat16 g_qb[(size_t)NQ * KF];
__device__ __nv_bfloat16 g_sb[(size_t)NS * KF];

// ---------------------------------------------------------------------------
// small PTX helpers
// ---------------------------------------------------------------------------
__device__ __forceinline__ uint32_t smem_u32(const void* p) {
    uint32_t a;
    asm("{ .reg .u64 t; cvta.to.shared.u64 t, %1; cvt.u32.u64 %0, t; }"
        : "=r"(a) : "l"(p));
    return a;
}

#if HAS_TCGEN05
__device__ __forceinline__ uint32_t elect_one() {
    uint32_t pred;
    asm volatile("{\n\t.reg .pred p;\n\telect.sync _|p, 0xFFFFFFFF;\n\t"
                 "selp.b32 %0, 1, 0, p;\n\t}" : "=r"(pred));
    return pred;
}
__device__ __forceinline__ void mbar_init(uint32_t addr, uint32_t cnt) {
    asm volatile("mbarrier.init.shared.b64 [%0], %1;" :: "r"(addr), "r"(cnt) : "memory");
}
__device__ __forceinline__ void mbar_wait(uint32_t addr, uint32_t parity) {
    asm volatile(
        "{\n\t.reg .pred P;\n\t"
        "WL_%=:\n\t"
        "mbarrier.try_wait.parity.shared::cta.b64 P, [%0], %1, 0x989680;\n\t"
        "@!P bra WL_%=;\n\t}"
        :: "r"(addr), "r"(parity) : "memory");
}
// SW128 K-major smem descriptor: layout=SW128(2), version=1, SBO=64, LBO=1
__device__ __forceinline__ uint64_t make_desc(uint32_t addr) {
    const uint64_t BASE = (2ull << 61) | (1ull << 46) | (64ull << 32) | (1ull << 16);
    return BASE | ((uint64_t)(addr >> 4) & 0x3FFF);
}
__device__ __forceinline__ void mma_f16_ss(uint32_t d, uint64_t ad, uint64_t bd,
                                           uint32_t idesc, bool accum) {
    uint32_t en = accum ? 1u : 0u;
    asm volatile(
        "{\n\t.reg .pred p;\n\t"
        "setp.ne.u32 p, %5, 0;\n\t"
        "tcgen05.mma.cta_group::1.kind::f16 [%0], %1, %2, %3, {%4,%4,%4,%4}, p;\n\t}"
        :: "r"(d), "l"(ad), "l"(bd), "r"(idesc), "r"(0u), "r"(en) : "memory");
}
// idesc kind::f16: dtype=F32(bit4), atype=btype=BF16(bits7,10), N>>3 @17 (6b), M>>4 @24
static constexpr uint32_t GEMM_IDESC =
    (1u << 4) | (1u << 7) | (1u << 10) | ((GN / 8) << 17) | ((GM / 16) << 24);
#endif

// ---------------------------------------------------------------------------
// Kernel 0: fp32 -> bf16 conversion of q and s (row-major, contiguous)
// ---------------------------------------------------------------------------
__global__ void convert_kernel(const float* __restrict__ q,
                               const float* __restrict__ s) {
    size_t i = (size_t)blockIdx.x * blockDim.x + threadIdx.x;
    const size_t nq4 = (size_t)NQ * KF / 4;
    const size_t tot = nq4 + (size_t)NS * KF / 4;
    if (i >= tot) return;
    float4 v;
    __nv_bfloat16* dst;
    if (i < nq4) { v = ((const float4*)q)[i]; dst = g_qb + i * 4; }
    else { size_t j = i - nq4; v = ((const float4*)s)[j]; dst = g_sb + j * 4; }
    __nv_bfloat162 lo = __float22bfloat162_rn(make_float2(v.x, v.y));
    __nv_bfloat162 hi = __float22bfloat162_rn(make_float2(v.z, v.w));
    uint2 u;
    u.x = *reinterpret_cast<uint32_t*>(&lo);
    u.y = *reinterpret_cast<uint32_t*>(&hi);
    *reinterpret_cast<uint2*>(dst) = u;
}

// ---------------------------------------------------------------------------
// Kernel 1: squared norms (one warp per row)
// ---------------------------------------------------------------------------
__global__ void norms_kernel(const float* __restrict__ q,
                             const float* __restrict__ s) {
    int gw   = (blockIdx.x * blockDim.x + threadIdx.x) >> 5;
    int lane = threadIdx.x & 31;
    if (gw >= NQ + NS) return;
    const float* base = (gw < NQ) ? (q + (size_t)gw * KF)
                                  : (s + (size_t)(gw - NQ) * KF);
    const float4* b4 = (const float4*)base;
    float sum = 0.f;
    #pragma unroll 4
    for (int i = lane; i < KF / 4; i += 32) {
        float4 v = b4[i];
        sum += v.x * v.x + v.y * v.y + v.z * v.z + v.w * v.w;
    }
    #pragma unroll
    for (int o = 16; o; o >>= 1) sum += __shfl_down_sync(0xffffffffu, sum, o);
    if (lane == 0) {
        if (gw < NQ) g_q2[gw] = sum;
        else         g_s2[gw - NQ] = sum;
    }
}

// ---------------------------------------------------------------------------
// Kernel 2: approx d2 GEMM. One kernel, two per-arch bodies:
//   sm_103a pass : tcgen05 bf16 SS MMA, 128x256 tile, TMEM accum
//   plain pass   : mma.sync.m16n8k16 bf16, two 128x128 halves per CTA
// grid = (NQ/GM, NS/GN) for both.
// ---------------------------------------------------------------------------
__global__ __launch_bounds__(256) __cluster_dims__(1, 1, 1)
void dist_gemm() {
    extern __shared__ __align__(16) char dynsmem[];
    const int tid  = threadIdx.x;
    const int wid  = tid >> 5;
    const int lane = tid & 31;
    const int m0 = blockIdx.x * GM;
    const int n0 = blockIdx.y * GN;

#if HAS_TCGEN05
    // =========================== tcgen05 path ===============================
    const uint32_t raw   = smem_u32(dynsmem);
    const uint32_t tile0 = (raw + 1023) & ~1023u;
    const uint32_t hdr   = tile0 + 2 * STAGE_BYTES;
    const uint32_t tmem_ptr_addr = hdr;
    const uint32_t mbar[2] = { hdr + 8, hdr + 16 };

    if (wid == 0) {
        asm volatile("tcgen05.alloc.cta_group::1.sync.aligned.shared::cta.b32 [%0], %1;"
                     :: "r"(tmem_ptr_addr), "r"(256u) : "memory");
        asm volatile("tcgen05.relinquish_alloc_permit.cta_group::1.sync.aligned;");
    }
    if (tid == 0) { mbar_init(mbar[0], 1); mbar_init(mbar[1], 1); }
    __syncthreads();
    uint32_t tmem;
    asm volatile("ld.shared.b32 %0, [%1];" : "=r"(tmem) : "r"(tmem_ptr_addr));

    const __nv_bfloat16* Aglob = g_qb + (size_t)m0 * KF;
    const __nv_bfloat16* Bglob = g_sb + (size_t)n0 * KF;

    uint32_t ph[2] = {0, 0};
    #pragma unroll 1
    for (int kt = 0; kt < KSLABS; kt++) {
        const int buf = kt & 1;
        const uint32_t Ab = tile0 + buf * STAGE_BYTES;
        const uint32_t Bb = Ab + A_STAGE_BYTES;
        if (kt >= 2) {                    // buffer reused: wait MMA of slab kt-2
            mbar_wait(mbar[buf], ph[buf]);
            ph[buf] ^= 1;
        }
        // load slab kt: 3072 16B chunks (A:1024, B:2048), SW128 swizzled stores
        {
            const uint4* As4 = (const uint4*)(Aglob + (size_t)kt * GBK);
            const uint4* Bs4 = (const uint4*)(Bglob + (size_t)kt * GBK);
            #pragma unroll
            for (int it = 0; it < 12; it++) {
                int idx = tid + it * 256;            // 0..3071
                bool isA = idx < GM * 8;
                int lidx = isA ? idx : idx - GM * 8;
                int row  = lidx >> 3;
                int ch   = lidx & 7;
                uint4 v = isA ? As4[(size_t)row * (KF / 8) + ch]
                              : Bs4[(size_t)row * (KF / 8) + ch];
                uint32_t off = row * 128 + ch * 16;
                uint32_t sw  = off ^ ((row & 7) << 4);   // SW128 swizzle
                uint32_t dst = (isA ? Ab : Bb) + sw;
                asm volatile("st.shared.v4.b32 [%0], {%1,%2,%3,%4};"
                             :: "r"(dst), "r"(v.x), "r"(v.y), "r"(v.z), "r"(v.w)
                             : "memory");
            }
        }
        asm volatile("fence.proxy.async.shared::cta;" ::: "memory");
        __syncthreads();
        if (wid == 0) {
            uint64_t ad = make_desc(Ab);
            uint64_t bd = make_desc(Bb);
            if (elect_one()) {
                #pragma unroll
                for (int st = 0; st < 4; st++)   // K16 steps within the slab
                    mma_f16_ss(tmem, ad + st * 2, bd + st * 2, GEMM_IDESC,
                               (kt > 0) || (st > 0));
                asm volatile(
                    "tcgen05.commit.cta_group::1.mbarrier::arrive::one.shared::cluster.b64 [%0];"
                    :: "r"(mbar[buf]) : "memory");
            }
        }
    }
    mbar_wait(mbar[0], ph[0]);
    mbar_wait(mbar[1], ph[1]);
    asm volatile("tcgen05.fence::after_thread_sync;" ::: "memory");

    // epilogue: warps 0-3 read D (128 lanes x 256 cols fp32) in 32-col chunks
    if (wid < 4) {
        const int row = m0 + wid * 32 + lane;
        const float q2v = g_q2[row];
        float* orow = g_d2 + (size_t)row * NS + n0;
        #pragma unroll 1
        for (int cb = 0; cb < 8; cb++) {
            uint32_t dr[32];
            asm volatile(
                "tcgen05.ld.sync.aligned.32x32b.x32.b32 "
                "{%0,%1,%2,%3,%4,%5,%6,%7,%8,%9,%10,%11,%12,%13,%14,%15,"
                "%16,%17,%18,%19,%20,%21,%22,%23,%24,%25,%26,%27,%28,%29,%30,%31}, [%32];"
                : "=r"(dr[0]), "=r"(dr[1]), "=r"(dr[2]), "=r"(dr[3]),
                  "=r"(dr[4]), "=r"(dr[5]), "=r"(dr[6]), "=r"(dr[7]),
                  "=r"(dr[8]), "=r"(dr[9]), "=r"(dr[10]), "=r"(dr[11]),
                  "=r"(dr[12]), "=r"(dr[13]), "=r"(dr[14]), "=r"(dr[15]),
                  "=r"(dr[16]), "=r"(dr[17]), "=r"(dr[18]), "=r"(dr[19]),
                  "=r"(dr[20]), "=r"(dr[21]), "=r"(dr[22]), "=r"(dr[23]),
                  "=r"(dr[24]), "=r"(dr[25]), "=r"(dr[26]), "=r"(dr[27]),
                  "=r"(dr[28]), "=r"(dr[29]), "=r"(dr[30]), "=r"(dr[31])
                : "r"(tmem + cb * 32));
            asm volatile("tcgen05.wait::ld.sync.aligned;" ::: "memory");
            const int nb = cb * 32;
            #pragma unroll
            for (int j = 0; j < 32; j += 4) {
                float4 o;
                o.x = q2v + g_s2[n0 + nb + j + 0] - 2.f * __uint_as_float(dr[j + 0]);
                o.y = q2v + g_s2[n0 + nb + j + 1] - 2.f * __uint_as_float(dr[j + 1]);
                o.z = q2v + g_s2[n0 + nb + j + 2] - 2.f * __uint_as_float(dr[j + 2]);
                o.w = q2v + g_s2[n0 + nb + j + 3] - 2.f * __uint_as_float(dr[j + 3]);
                *(float4*)(orow + nb + j) = o;
            }
        }
    }
    __syncthreads();
    if (wid == 0) {
        asm volatile("tcgen05.dealloc.cta_group::1.sync.aligned.b32 %0, %1;"
                     :: "r"(tmem), "r"(256u));
    }
#else
    // ======================= mma.sync fallback path =========================
    // Two 128x128 halves; double-buffered smem; 8 warps x (64M x 32N).
    __nv_bfloat16* As = (__nv_bfloat16*)dynsmem;              // [2][128*32]
    __nv_bfloat16* Bs = As + 2 * 128 * 32;                    // [2][128*32]
    const int wm = (wid & 1) * 64;
    const int wn = (wid >> 1) * 32;

    #pragma unroll 1
    for (int nh = 0; nh < 2; nh++) {
        const int n0h = n0 + nh * 128;
        float acc[4][4][4];
        #pragma unroll
        for (int mt = 0; mt < 4; mt++)
            #pragma unroll
            for (int nt = 0; nt < 4; nt++)
                #pragma unroll
                for (int c = 0; c < 4; c++) acc[mt][nt][c] = 0.f;

        uint4 ra2[2], rb2[2];
        auto gload = [&](int kt) {
            const uint4* Ag = (const uint4*)(g_qb + (size_t)m0 * KF);
            const uint4* Bg = (const uint4*)(g_sb + (size_t)n0h * KF);
            #pragma unroll
            for (int it = 0; it < 2; it++) {
                int idx = tid + it * 256;          // 0..511
                int row = idx >> 2;                // 0..127
                int ch  = idx & 3;                 // 16B chunk in 64B row
                ra2[it] = Ag[(size_t)row * (KF / 8) + kt * 4 + ch];
                rb2[it] = Bg[(size_t)row * (KF / 8) + kt * 4 + ch];
            }
        };
        auto sstore = [&](int buf) {
            #pragma unroll
            for (int it = 0; it < 2; it++) {
                int idx = tid + it * 256;
                int row = idx >> 2;
                int ch  = idx & 3;
                int pc  = ch ^ ((row >> 1) & 3);
                int off = row * 64 + pc * 16;
                *(uint4*)((char*)(As + buf * 128 * 32) + off) = ra2[it];
                *(uint4*)((char*)(Bs + buf * 128 * 32) + off) = rb2[it];
            }
        };
        auto compute = [&](int buf) {
            const char* Ab = (const char*)(As + buf * 128 * 32);
            const char* Bb = (const char*)(Bs + buf * 128 * 32);
            #pragma unroll
            for (int ks = 0; ks < 2; ks++) {
                const int c0 = ks * 2, c1 = ks * 2 + 1;
                const int by = (lane & 3) * 4;
                uint32_t afr[4][4], bfr[4][2];
                #pragma unroll
                for (int mt = 0; mt < 4; mt++) {
                    int r0 = wm + mt * 16 + (lane >> 2);
                    int r1 = r0 + 8;
                    afr[mt][0] = *(const uint32_t*)(Ab + r0 * 64 + (c0 ^ ((r0 >> 1) & 3)) * 16 + by);
                    afr[mt][1] = *(const uint32_t*)(Ab + r1 * 64 + (c0 ^ ((r1 >> 1) & 3)) * 16 + by);
                    afr[mt][2] = *(const uint32_t*)(Ab + r0 * 64 + (c1 ^ ((r0 >> 1) & 3)) * 16 + by);
                    afr[mt][3] = *(const uint32_t*)(Ab + r1 * 64 + (c1 ^ ((r1 >> 1) & 3)) * 16 + by);
                }
                #pragma unroll
                for (int nt = 0; nt < 4; nt++) {
                    int nr = wn + nt * 8 + (lane >> 2);
                    bfr[nt][0] = *(const uint32_t*)(Bb + nr * 64 + (c0 ^ ((nr >> 1) & 3)) * 16 + by);
                    bfr[nt][1] = *(const uint32_t*)(Bb + nr * 64 + (c1 ^ ((nr >> 1) & 3)) * 16 + by);
                }
                #pragma unroll
                for (int mt = 0; mt < 4; mt++)
                    #pragma unroll
                    for (int nt = 0; nt < 4; nt++)
                        asm volatile(
                            "mma.sync.aligned.m16n8k16.row.col.f32.bf16.bf16.f32 "
                            "{%0,%1,%2,%3}, {%4,%5,%6,%7}, {%8,%9}, {%0,%1,%2,%3};\n"
                            : "+f"(acc[mt][nt][0]), "+f"(acc[mt][nt][1]),
                              "+f"(acc[mt][nt][2]), "+f"(acc[mt][nt][3])
                            : "r"(afr[mt][0]), "r"(afr[mt][1]),
                              "r"(afr[mt][2]), "r"(afr[mt][3]),
                              "r"(bfr[nt][0]), "r"(bfr[nt][1]));
            }
        };

        gload(0);
        sstore(0);
        __syncthreads();
        int buf = 0;
        #pragma unroll 1
        for (int kt = 0; kt < KF / 32; kt++) {
            if (kt + 1 < KF / 32) gload(kt + 1);
            compute(buf);
            if (kt + 1 < KF / 32) {
                sstore(buf ^ 1);
                __syncthreads();
                buf ^= 1;
            }
        }
        __syncthreads();

        #pragma unroll
        for (int mt = 0; mt < 4; mt++) {
            int rlo = m0 + wm + mt * 16 + (lane >> 2);
            float q2lo = g_q2[rlo];
            float q2hi = g_q2[rlo + 8];
            #pragma unroll
            for (int nt = 0; nt < 4; nt++) {
                int nc = n0h + wn + nt * 8 + (lane & 3) * 2;
                float s20 = g_s2[nc], s21 = g_s2[nc + 1];
                float2 o;
                o.x = q2lo + s20 - 2.f * acc[mt][nt][0];
                o.y = q2lo + s21 - 2.f * acc[mt][nt][1];
                *(float2*)(g_d2 + (size_t)rlo * NS + nc) = o;
                o.x = q2hi + s20 - 2.f * acc[mt][nt][2];
                o.y = q2hi + s21 - 2.f * acc[mt][nt][3];
                *(float2*)(g_d2 + (size_t)(rlo + 8) * NS + nc) = o;
            }
        }
    }
#endif
}

// ---------------------------------------------------------------------------
// Kernel 3: per-query approx top-16 -> threshold -> candidate list.
// ---------------------------------------------------------------------------
__global__ __launch_bounds__(256)
void topk_select_kernel() {
    const int qrow = blockIdx.x;
    const int tid  = threadIdx.x;
    const float* row = g_d2 + (size_t)qrow * NS;

    float lv[KSEL];
    int   li[KSEL];
    #pragma unroll
    for (int i = 0; i < KSEL; i++) { lv[i] = CUDART_INF_F; li[i] = 0x7fffffff; }
    float worst = CUDART_INF_F;

    const float4* row4 = (const float4*)row;
    for (int j4 = tid; j4 < NS / 4; j4 += 256) {
        float4 v4 = row4[j4];
        float vs[4] = {v4.x, v4.y, v4.z, v4.w};
        #pragma unroll
        for (int c = 0; c < 4; c++) {
            float v = vs[c];
            if (v < worst) {
                int j = j4 * 4 + c;
                int pos = KSEL - 1;
                #pragma unroll
                for (int t = KSEL - 1; t > 0; t--) {
                    if (pos == t && v < lv[t - 1]) {
                        lv[t] = lv[t - 1]; li[t] = li[t - 1]; pos = t - 1;
                    }
                }
                lv[pos] = v; li[pos] = j;
                worst = lv[KSEL - 1];
            }
        }
    }

    __shared__ float sv[256];
    __shared__ int   si[256];
    __shared__ float T_s;
    __shared__ int   cnt;

    int p = 0;
    for (int r = 0; r < KSEL; r++) {
        sv[tid] = (p < KSEL) ? lv[p] : CUDART_INF_F;
        si[tid] = (p < KSEL) ? li[p] : 0x7fffffff;
        __syncthreads();
        #pragma unroll
        for (int s = 128; s > 0; s >>= 1) {
            if (tid < s) {
                float v2 = sv[tid + s]; int i2 = si[tid + s];
                if (v2 < sv[tid] || (v2 == sv[tid] && i2 < si[tid])) {
                    sv[tid] = v2; si[tid] = i2;
                }
            }
            __syncthreads();
        }
        int winIdx = si[0];
        if (r == KSEL - 1 && tid == 0) { T_s = sv[0]; cnt = 0; }
        if (p < KSEL && li[p] == winIdx) p++;
        __syncthreads();
    }

    const float thresh = T_s + MARGIN;
    for (int j4 = tid; j4 < NS / 4; j4 += 256) {
        float4 v4 = row4[j4];
        float vs[4] = {v4.x, v4.y, v4.z, v4.w};
        #pragma unroll
        for (int c = 0; c < 4; c++) {
            if (vs[c] <= thresh) {
                int slot = atomicAdd(&cnt, 1);
                if (slot < NCAND) g_cand[(size_t)qrow * NCAND + slot] = j4 * 4 + c;
            }
        }
    }
    __syncthreads();
    if (tid == 0) g_ccount[qrow] = (cnt < NCAND) ? cnt : NCAND;
}

// ---------------------------------------------------------------------------
// Kernel 4: exact fp32 refinement + final top-16 + weights.
// Output layout (float32): [ indices (NQ*16) | weights (NQ*16) ]
// ---------------------------------------------------------------------------
__global__ __launch_bounds__(256)
void refine_kernel(const float* __restrict__ q,
                   const float* __restrict__ s,
                   float* __restrict__ out) {
    const int qrow = blockIdx.x;
    const int tid  = threadIdx.x;
    const int warp = tid >> 5;
    const int lane = tid & 31;

    __shared__ float qs[KF];
    __shared__ float ev[NCAND];
    __shared__ int   ei[NCAND];
    __shared__ float sv[128];
    __shared__ int   si[128];
    __shared__ float resv[KSEL];
    __shared__ int   resi[KSEL];

    const int m = g_ccount[qrow];

    for (int i = tid; i < KF; i += 256) qs[i] = q[(size_t)qrow * KF + i];
    for (int i = tid; i < NCAND; i += 256) { ev[i] = CUDART_INF_F; ei[i] = 0x7fffffff; }
    __syncthreads();

    const float q2v = g_q2[qrow];
    for (int ci = warp; ci < m; ci += 8) {
        int sidx = g_cand[(size_t)qrow * NCAND + ci];
        const float* srow = s + (size_t)sidx * KF;
        float dot = 0.f;
        #pragma unroll
        for (int t = 0; t < KF / 32; t++)
            dot = fmaf(qs[lane + 32 * t], srow[lane + 32 * t], dot);
        #pragma unroll
        for (int o = 16; o; o >>= 1) dot += __shfl_down_sync(0xffffffffu, dot, o);
        if (lane == 0) {
            ev[ci] = q2v + g_s2[sidx] - 2.f * dot;
            ei[ci] = sidx;
        }
    }
    __syncthreads();

    for (int r = 0; r < KSEL; r++) {
        if (tid < 128) { sv[tid] = ev[tid]; si[tid] = ei[tid]; }
        __syncthreads();
        #pragma unroll
        for (int st = 64; st > 0; st >>= 1) {
            if (tid < st) {
                float v2 = sv[tid + st]; int i2 = si[tid + st];
                if (v2 < sv[tid] || (v2 == sv[tid] && i2 < si[tid])) {
                    sv[tid] = v2; si[tid] = i2;
                }
            }
            __syncthreads();
        }
        if (tid == 0) { resv[r] = sv[0]; resi[r] = si[0]; }
        __syncthreads();
        if (tid < 128 && ei[tid] == si[0]) ev[tid] = CUDART_INF_F;
        __syncthreads();
    }

    if (tid == 0) {
        float w[KSEL];
        float ssum = 0.f;
        #pragma unroll
        for (int r = 0; r < KSEL; r++) {
            float d = sqrtf(fmaxf(resv[r], 1e-12f));
            w[r] = 1.f / (d + 1e-6f);
            ssum += w[r];
        }
        float inv = 1.f / ssum;
        #pragma unroll
        for (int r = 0; r < KSEL; r++) {
            out[(size_t)qrow * KSEL + r] = (float)resi[r];
            out[(size_t)NQ * KSEL + (size_t)qrow * KSEL + r] = w[r] * inv;
        }
    }
}

// ---------------------------------------------------------------------------
extern "C" void kernel_launch(void* const* d_in, const int* in_sizes, int n_in,
                              void* d_out, int out_size) {
    const float* q = (const float*)d_in[0];  // (2048, 32, 16) -> (2048, 512)
    const float* s = (const float*)d_in[1];  // (65536, 32, 16) -> (65536, 512)
    float* out = (float*)d_out;

    // allow >48KB dynamic smem for the GEMM (host attr, immediate, not a node)
    static bool attr_done = false;
    if (!attr_done) {
        cudaFuncSetAttribute(dist_gemm,
                             cudaFuncAttributeMaxDynamicSharedMemorySize,
                             GEMM_DYN_SMEM);
        attr_done = true;
    }

    // 0) fp32 -> bf16 conversion
    {
        size_t tot = ((size_t)NQ + NS) * KF / 4;
        int nb = (int)((tot + 255) / 256);
        convert_kernel<<<nb, 256>>>(q, s);
    }

    // 1) exact fp32 norms
    int rows = NQ + NS;
    int nblocks = (rows * 32 + 255) / 256;
    norms_kernel<<<nblocks, 256>>>(q, s);

    // 2) approx distance GEMM. grid.x = M blocks (fast) -> B reuse in L2.
    dim3 g(NQ / GM, NS / GN);
    dist_gemm<<<g, 256, GEMM_DYN_SMEM>>>();

    // 3) approx top-16 + candidate collection
    topk_select_kernel<<<NQ, 256>>>();

    // 4) exact refinement + output
    refine_kernel<<<NQ, 256>>>(q, s, out);
}